// round 4
// baseline (speedup 1.0000x reference)
#include <cuda_runtime.h>
#include <cstdint>

// Problem constants
#define Nn 20000
#define Ee 320000
#define Bb 2
#define INF_DIM 32
#define HIDD 64
#define HEADS 4
#define OUTD 8
#define SLOPE 0.2f

#define NB (Nn*Bb)              // 40000
#define FTC (HEADS*HIDD)        // 256

// Scratch (device globals)
__device__ __align__(16) float g_x[NB*HIDD];
__device__ __align__(16) float g_ft[(size_t)NB*FTC];
__device__ __align__(16) float g_res[NB*HIDD];
__device__ float g_el[NB*HEADS];   // [node*8 + b*4 + h]
__device__ float g_er[NB*HEADS];
__device__ float g_Pl[HIDD*HEADS];
__device__ float g_Pr[HIDD*HEADS];
__device__ int g_deg[Nn];
__device__ int g_fill[Nn];
__device__ int g_rowptr[Nn + 1];
__device__ int g_col[Ee];

// ---------------- CSR build ----------------
__global__ void zero_k() {
    int idx = blockIdx.x * blockDim.x + threadIdx.x;
    if (idx < Nn) { g_deg[idx] = 0; g_fill[idx] = 0; }
}

__global__ void hist_k(const int* __restrict__ ei) {
    int idx = blockIdx.x * blockDim.x + threadIdx.x;
    if (idx < Ee) atomicAdd(&g_deg[ei[Ee + idx]], 1);
}

// single-block exclusive scan of g_deg[0..Nn) -> g_rowptr
__global__ void scan_k() {
    __shared__ int wsum[32];
    __shared__ int woff[32];
    __shared__ int btot_s;
    int tid = threadIdx.x;
    int lane = tid & 31, wid = tid >> 5;
    int carry = 0;
    for (int base = 0; base < Nn; base += 1024) {
        int i = base + tid;
        int v = (i < Nn) ? g_deg[i] : 0;
        int incl = v;
#pragma unroll
        for (int o = 1; o < 32; o <<= 1) {
            int t = __shfl_up_sync(0xffffffffu, incl, o);
            if (lane >= o) incl += t;
        }
        if (lane == 31) wsum[wid] = incl;
        __syncthreads();
        if (tid < 32) {
            int wv = wsum[tid];
            int wincl = wv;
#pragma unroll
            for (int o = 1; o < 32; o <<= 1) {
                int t = __shfl_up_sync(0xffffffffu, wincl, o);
                if (tid >= o) wincl += t;
            }
            woff[tid] = wincl - wv;
            if (tid == 31) btot_s = wincl;
        }
        __syncthreads();
        if (i < Nn) g_rowptr[i] = carry + woff[wid] + (incl - v);
        int btot = btot_s;
        __syncthreads();
        carry += btot;
    }
    if (tid == 0) g_rowptr[Nn] = carry;
}

__global__ void fill_k(const int* __restrict__ ei) {
    int idx = blockIdx.x * blockDim.x + threadIdx.x;
    if (idx >= Ee) return;
    int d = ei[Ee + idx];
    int pos = g_rowptr[d] + atomicAdd(&g_fill[d], 1);
    g_col[pos] = ei[idx];
}

// ---------------- projections P_l/P_r = reshape(W_gat) @ a ----------------
__global__ void proj_k(const float* __restrict__ W_gat, const float* __restrict__ a_l,
                       const float* __restrict__ a_r) {
    int t = threadIdx.x;         // 256 threads
    int k = t >> 2, h = t & 3;
    float sl = 0.f, sr = 0.f;
#pragma unroll
    for (int d = 0; d < HIDD; d++) {
        float wv = W_gat[k*FTC + h*HIDD + d];
        sl += wv * a_l[h*HIDD + d];
        sr += wv * a_r[h*HIDD + d];
    }
    g_Pl[k*4 + h] = sl;
    g_Pr[k*4 + h] = sr;
}

// ---------------- encoder: x[n,b,:] = h[b,n,:] @ W_enc + b_enc ----------------
__global__ void enc_k(const float* __restrict__ h, const float* __restrict__ W_enc,
                      const float* __restrict__ b_enc) {
    int idx = blockIdx.x * blockDim.x + threadIdx.x;
    if (idx >= NB*HIDD) return;
    int d  = idx & 63;
    int nb = idx >> 6;
    int n = nb >> 1, b = nb & 1;
    const float* hr = &h[((size_t)b*Nn + n)*INF_DIM];
    float acc = b_enc[d];
#pragma unroll
    for (int k = 0; k < INF_DIM; k++) acc += hr[k] * W_enc[k*HIDD + d];
    g_x[idx] = acc;
}

// ---------------- ft = x @ W_gat, res = x @ W_res + b_res ----------------
// block: 256 threads, 32 rows of x. thread t owns ft output column t.
#define FTROWS 32
__global__ void ft_k(const float* __restrict__ W_gat,
                     const float* __restrict__ W_res, const float* __restrict__ b_res) {
    __shared__ float xs[FTROWS][HIDD];
    int t = threadIdx.x;
    int nb0 = blockIdx.x * FTROWS;

    for (int i = t; i < FTROWS*HIDD; i += 256)
        xs[i >> 6][i & 63] = g_x[(size_t)nb0*HIDD + i];
    __syncthreads();

    float acc[FTROWS];
#pragma unroll
    for (int r = 0; r < FTROWS; r++) acc[r] = 0.f;

    for (int k = 0; k < HIDD; k++) {
        float wv = W_gat[k*FTC + t];
#pragma unroll
        for (int r = 0; r < FTROWS; r++) acc[r] += xs[r][k] * wv;
    }
#pragma unroll
    for (int r = 0; r < FTROWS; r++)
        g_ft[((size_t)(nb0 + r))*FTC + t] = acc[r];

    // res: thread t computes col c for 8 rows (rr, rr+4, ..., rr+28)
    {
        int c = t & 63, rr = t >> 6;
        float rv[8];
        float bb = b_res[c];
#pragma unroll
        for (int i = 0; i < 8; i++) rv[i] = bb;
        for (int k = 0; k < HIDD; k++) {
            float wv = W_res[k*HIDD + c];
#pragma unroll
            for (int i = 0; i < 8; i++)
                rv[i] += xs[rr + i*4][k] * wv;
        }
#pragma unroll
        for (int i = 0; i < 8; i++)
            g_res[(size_t)(nb0 + rr + i*4)*HIDD + c] = rv[i];
    }
}

// ---------------- el/er: [NB,8] = x @ [P_l | P_r] ----------------
// block: 256 threads = 32 rows x 8 cols
__global__ void elr_k() {
    __shared__ float xs[32][HIDD];
    int t = threadIdx.x;
    int nb0 = blockIdx.x * 32;
    for (int i = t; i < 32*HIDD; i += 256)
        xs[i >> 6][i & 63] = g_x[(size_t)nb0*HIDD + i];
    __syncthreads();
    int r = t >> 3, q = t & 7;
    const float* P = (q < 4) ? g_Pl : g_Pr;
    int h = q & 3;
    float acc = 0.f;
#pragma unroll
    for (int k = 0; k < HIDD; k++) acc += xs[r][k] * P[k*4 + h];
    int nb = nb0 + r;               // el layout index: nb*4 + h == node*8 + b*4 + h
    if (q < 4) g_el[nb*4 + h] = acc;
    else       g_er[nb*4 + h] = acc;
}

// ---------------- fused node-centric GAT aggregation + update ----------------
// one warp per (dst node, batch). No max-shift (values are small; softmax is
// shift-invariant). Chunked 8 edges at a time for memory-level parallelism.
__global__ void node_agg_k(const float* __restrict__ b_gat) {
    int gw = (blockIdx.x * blockDim.x + threadIdx.x) >> 5;
    int lane = threadIdx.x & 31;
    if (gw >= NB) return;
    int w = gw >> 1, b = gw & 1;
    int beg = g_rowptr[w], end = g_rowptr[w + 1];

    // broadcast er[w,b,h] (4 values)
    float er_v = (lane < 4) ? g_er[w*8 + b*4 + lane] : 0.f;
    float er_all[4];
#pragma unroll
    for (int j = 0; j < 4; j++) er_all[j] = __shfl_sync(0xffffffffu, er_v, j);

    int jj = lane >> 2, hh = lane & 3;   // lane -> (edge-in-chunk, head)

    // Pass 1: z[h] = sum_e exp(leaky(el[s]+er[d]))
    float zpart = 0.f;
    for (int i0 = beg; i0 < end; i0 += 8) {
        int i = i0 + jj;
        if (i < end) {
            int s = g_col[i];
            float v = g_el[s*8 + b*4 + hh] + er_all[hh];
            v = v > 0.f ? v : SLOPE * v;
            zpart += __expf(v);
        }
    }
#pragma unroll
    for (int o = 4; o < 32; o <<= 1)
        zpart += __shfl_xor_sync(0xffffffffu, zpart, o);
    float rz_mine = 0.25f / zpart;       // fold head-mean; replicated per h
    float rz[4];
#pragma unroll
    for (int h = 0; h < 4; h++) rz[h] = __shfl_sync(0xffffffffu, rz_mine, h);

    // Pass 2: weighted gather; lane owns dims [lane*2, lane*2+2)
    float2 acc = make_float2(0.f, 0.f);
    for (int i0 = beg; i0 < end; i0 += 8) {
        int i = i0 + jj;
        float a = 0.f;
        int sj = 0;
        if (i < end) {
            sj = g_col[i];
            float v = g_el[sj*8 + b*4 + hh] + er_all[hh];
            v = v > 0.f ? v : SLOPE * v;
            a = __expf(v) * rz[hh];
        }
        int nE = end - i0; if (nE > 8) nE = 8;
#pragma unroll
        for (int j = 0; j < 8; j++) {
            if (j >= nE) break;
            int s   = __shfl_sync(0xffffffffu, sj, j*4);
            float a0 = __shfl_sync(0xffffffffu, a, j*4 + 0);
            float a1 = __shfl_sync(0xffffffffu, a, j*4 + 1);
            float a2 = __shfl_sync(0xffffffffu, a, j*4 + 2);
            float a3 = __shfl_sync(0xffffffffu, a, j*4 + 3);
            const float2* f = (const float2*)&g_ft[((size_t)(s*2 + b))*FTC];
            float2 v0 = f[lane];
            float2 v1 = f[32 + lane];
            float2 v2 = f[64 + lane];
            float2 v3 = f[96 + lane];
            acc.x += a0*v0.x + a1*v1.x + a2*v2.x + a3*v3.x;
            acc.y += a0*v0.y + a1*v1.y + a2*v2.y + a3*v3.y;
        }
    }

    // epilogue: + mean_h(b_gat) + res, ELU, write x
    int d0 = lane*2;
    float bg0 = 0.25f*(b_gat[d0]   + b_gat[64 + d0]   + b_gat[128 + d0]   + b_gat[192 + d0]);
    float bg1 = 0.25f*(b_gat[d0+1] + b_gat[64 + d0+1] + b_gat[128 + d0+1] + b_gat[192 + d0+1]);

    float2 rv = ((const float2*)&g_res[((size_t)(w*2 + b))*HIDD])[lane];
    float ox = acc.x + bg0 + rv.x;
    float oy = acc.y + bg1 + rv.y;
    ox = ox > 0.f ? ox : expm1f(ox);
    oy = oy > 0.f ? oy : expm1f(oy);
    ((float2*)&g_x[((size_t)(w*2 + b))*HIDD])[lane] = make_float2(ox, oy);
}

// ---------------- decoder: out[b,n,:] = x[n,b,:] @ W_dec + b_dec ----------------
__global__ void dec_k(const float* __restrict__ W_dec, const float* __restrict__ b_dec,
                      float* __restrict__ out) {
    int idx = blockIdx.x * blockDim.x + threadIdx.x;
    if (idx >= NB*OUTD) return;
    int o = idx & 7;
    int nb = idx >> 3;
    int n = nb >> 1, b = nb & 1;
    const float* xr = &g_x[(size_t)nb*HIDD];
    float acc = b_dec[o];
#pragma unroll
    for (int k = 0; k < HIDD; k++) acc += xr[k] * W_dec[k*OUTD + o];
    out[((size_t)b*Nn + n)*OUTD + o] = acc;
}

extern "C" void kernel_launch(void* const* d_in, const int* in_sizes, int n_in,
                              void* d_out, int out_size) {
    const float* h     = (const float*)d_in[0];
    const int*   ei    = (const int*)  d_in[1];
    const float* W_enc = (const float*)d_in[2];
    const float* b_enc = (const float*)d_in[3];
    const float* W_gat = (const float*)d_in[4];
    const float* a_l   = (const float*)d_in[5];
    const float* a_r   = (const float*)d_in[6];
    const float* b_gat = (const float*)d_in[7];
    const float* W_res = (const float*)d_in[8];
    const float* b_res = (const float*)d_in[9];
    const float* W_dec = (const float*)d_in[10];
    const float* b_dec = (const float*)d_in[11];
    float* out = (float*)d_out;

    // CSR build (every call; graph-replay safe)
    zero_k<<<(Nn + 255)/256, 256>>>();
    hist_k<<<(Ee + 255)/256, 256>>>(ei);
    scan_k<<<1, 1024>>>();
    fill_k<<<(Ee + 255)/256, 256>>>(ei);

    proj_k<<<1, 256>>>(W_gat, a_l, a_r);
    enc_k<<<(NB*HIDD + 255)/256, 256>>>(h, W_enc, b_enc);

    for (int it = 0; it < 2; ++it) {
        ft_k<<<NB/FTROWS, 256>>>(W_gat, W_res, b_res);
        elr_k<<<NB/32, 256>>>();
        node_agg_k<<<(NB*32 + 255)/256, 256>>>(b_gat);
    }

    dec_k<<<(NB*OUTD + 255)/256, 256>>>(W_dec, b_dec, out);
}

// round 5
// speedup vs baseline: 1.0992x; 1.0992x over previous
#include <cuda_runtime.h>
#include <cstdint>

// Problem constants
#define Nn 20000
#define Ee 320000
#define Bb 2
#define INF_DIM 32
#define HIDD 64
#define HEADS 4
#define OUTD 8
#define SLOPE 0.2f

#define NB (Nn*Bb)              // 40000
#define FTC (HEADS*HIDD)        // 256

// Scratch (device globals)
__device__ __align__(16) float g_x[NB*HIDD];
__device__ __align__(16) float g_ft[(size_t)NB*FTC];
__device__ __align__(16) float g_res[NB*HIDD];
__device__ float g_el[NB*HEADS];   // [node*8 + b*4 + h]
__device__ float g_er[NB*HEADS];
__device__ int g_deg[Nn];
__device__ int g_fill[Nn];
__device__ int g_rowptr[Nn + 1];
__device__ int g_col[Ee];

// ---------------- CSR build ----------------
__global__ void zero_k() {
    int idx = blockIdx.x * blockDim.x + threadIdx.x;
    if (idx < Nn) { g_deg[idx] = 0; g_fill[idx] = 0; }
}

__global__ void hist_k(const int* __restrict__ ei) {
    int idx = blockIdx.x * blockDim.x + threadIdx.x;
    if (idx < Ee) atomicAdd(&g_deg[ei[Ee + idx]], 1);
}

// single-block exclusive scan of g_deg[0..Nn) -> g_rowptr
__global__ void scan_k() {
    __shared__ int wsum[32];
    __shared__ int woff[32];
    __shared__ int btot_s;
    int tid = threadIdx.x;
    int lane = tid & 31, wid = tid >> 5;
    int carry = 0;
    for (int base = 0; base < Nn; base += 1024) {
        int i = base + tid;
        int v = (i < Nn) ? g_deg[i] : 0;
        int incl = v;
#pragma unroll
        for (int o = 1; o < 32; o <<= 1) {
            int t = __shfl_up_sync(0xffffffffu, incl, o);
            if (lane >= o) incl += t;
        }
        if (lane == 31) wsum[wid] = incl;
        __syncthreads();
        if (tid < 32) {
            int wv = wsum[tid];
            int wincl = wv;
#pragma unroll
            for (int o = 1; o < 32; o <<= 1) {
                int t = __shfl_up_sync(0xffffffffu, wincl, o);
                if (tid >= o) wincl += t;
            }
            woff[tid] = wincl - wv;
            if (tid == 31) btot_s = wincl;
        }
        __syncthreads();
        if (i < Nn) g_rowptr[i] = carry + woff[wid] + (incl - v);
        int btot = btot_s;
        __syncthreads();
        carry += btot;
    }
    if (tid == 0) g_rowptr[Nn] = carry;
}

__global__ void fill_k(const int* __restrict__ ei) {
    int idx = blockIdx.x * blockDim.x + threadIdx.x;
    if (idx >= Ee) return;
    int d = ei[Ee + idx];
    int pos = g_rowptr[d] + atomicAdd(&g_fill[d], 1);
    g_col[pos] = ei[idx];
}

// ---------------- encoder: x[n,b,:] = h[b,n,:] @ W_enc + b_enc ----------------
__global__ void enc_k(const float* __restrict__ h, const float* __restrict__ W_enc,
                      const float* __restrict__ b_enc) {
    int idx = blockIdx.x * blockDim.x + threadIdx.x;
    if (idx >= NB*HIDD) return;
    int d  = idx & 63;
    int nb = idx >> 6;
    int n = nb >> 1, b = nb & 1;
    const float* hr = &h[((size_t)b*Nn + n)*INF_DIM];
    float acc = b_enc[d];
#pragma unroll
    for (int k = 0; k < INF_DIM; k++) acc += hr[k] * W_enc[k*HIDD + d];
    g_x[idx] = acc;
}

// ---------------- ft = x @ W_gat (+ fused el/er, res = x @ W_res + b_res) ----------------
// block: 256 threads, 16 rows of x. thread t owns ft output column t.
#define FTROWS 16
__global__ void ft_k(const float* __restrict__ W_gat, const float* __restrict__ a_l,
                     const float* __restrict__ a_r,
                     const float* __restrict__ W_res, const float* __restrict__ b_res) {
    __shared__ float xs[FTROWS][HIDD];
    __shared__ float els[FTROWS][HEADS];
    __shared__ float ers[FTROWS][HEADS];
    int t = threadIdx.x;
    int nb0 = blockIdx.x * FTROWS;

    for (int i = t; i < FTROWS*HIDD; i += 256)
        xs[i >> 6][i & 63] = g_x[(size_t)nb0*HIDD + i];
    if (t < FTROWS*HEADS) { els[t >> 2][t & 3] = 0.f; ers[t >> 2][t & 3] = 0.f; }
    __syncthreads();

    float acc[FTROWS];
#pragma unroll
    for (int r = 0; r < FTROWS; r++) acc[r] = 0.f;

    for (int k = 0; k < HIDD; k++) {
        float wv = W_gat[k*FTC + t];
#pragma unroll
        for (int r = 0; r < FTROWS; r++) acc[r] += xs[r][k] * wv;
    }

    float al = a_l[t];
    float ar = a_r[t];
    int hh = t >> 6;
#pragma unroll
    for (int r = 0; r < FTROWS; r++) {
        g_ft[((size_t)(nb0 + r))*FTC + t] = acc[r];
        float pl = acc[r] * al;
        float pr = acc[r] * ar;
#pragma unroll
        for (int o = 16; o > 0; o >>= 1) {
            pl += __shfl_xor_sync(0xffffffffu, pl, o);
            pr += __shfl_xor_sync(0xffffffffu, pr, o);
        }
        if ((t & 31) == 0) {
            atomicAdd(&els[r][hh], pl);
            atomicAdd(&ers[r][hh], pr);
        }
    }

    // res = x @ W_res + b_res : thread t computes col c for 4 rows
    {
        int c = t & 63, rr = t >> 6;
        float r0 = b_res[c], r1 = r0, r2 = r0, r3 = r0;
        for (int k = 0; k < HIDD; k++) {
            float wv = W_res[k*HIDD + c];
            r0 += xs[rr][k] * wv;
            r1 += xs[rr + 4][k] * wv;
            r2 += xs[rr + 8][k] * wv;
            r3 += xs[rr + 12][k] * wv;
        }
        g_res[(size_t)(nb0 + rr)*HIDD + c] = r0;
        g_res[(size_t)(nb0 + rr + 4)*HIDD + c] = r1;
        g_res[(size_t)(nb0 + rr + 8)*HIDD + c] = r2;
        g_res[(size_t)(nb0 + rr + 12)*HIDD + c] = r3;
    }

    __syncthreads();
    if (t < FTROWS*HEADS) {
        int r = t >> 2, h2 = t & 3;
        g_el[(nb0 + r)*HEADS + h2] = els[r][h2];
        g_er[(nb0 + r)*HEADS + h2] = ers[r][h2];
    }
}

// ---------------- fused node-centric GAT aggregation + update (ONE PASS) ----------------
// one warp per dst node, both batches. Softmax without max-shift (logits are
// O(1); exp safe in fp32). Normalization deferred: per-head unnormalized
// accumulators + redundant z[8] per lane, normalized in epilogue.
__global__ void node_agg_k(const float* __restrict__ b_gat) {
    int w = (blockIdx.x * blockDim.x + threadIdx.x) >> 5;
    int lane = threadIdx.x & 31;
    if (w >= Nn) return;
    int beg = g_rowptr[w], end = g_rowptr[w + 1];

    // broadcast er[w, b, h] (8 values) to all lanes
    float er_v = (lane < 8) ? g_er[w*8 + lane] : 0.f;
    float er_all[8];
#pragma unroll
    for (int j = 0; j < 8; j++) er_all[j] = __shfl_sync(0xffffffffu, er_v, j);

    float z[8];
    float2 acc[8];                 // [b*4 + hq], unnormalized
#pragma unroll
    for (int j = 0; j < 8; j++) { z[j] = 0.f; acc[j] = make_float2(0.f, 0.f); }

    for (int i0 = beg; i0 < end; i0 += 32) {
        int sj = (i0 + lane < end) ? g_col[i0 + lane] : 0;
        int nE = end - i0; if (nE > 32) nE = 32;
        for (int j = 0; j < nE; j++) {
            int s = __shfl_sync(0xffffffffu, sj, j);
            float e = 0.f;
            if (lane < 8) {
                float v = g_el[s*8 + lane] + er_all[lane];
                v = v > 0.f ? v : SLOPE * v;
                e = __expf(v);
            }
            float al[8];
#pragma unroll
            for (int jj = 0; jj < 8; jj++) {
                al[jj] = __shfl_sync(0xffffffffu, e, jj);
                z[jj] += al[jj];
            }
            const float2* f0 = (const float2*)&g_ft[((size_t)(s*2))*FTC];
            const float2* f1 = (const float2*)&g_ft[((size_t)(s*2 + 1))*FTC];
#pragma unroll
            for (int hq = 0; hq < 4; hq++) {
                float2 v0 = f0[hq*32 + lane];
                float2 v1 = f1[hq*32 + lane];
                acc[hq].x     += al[hq]     * v0.x;  acc[hq].y     += al[hq]     * v0.y;
                acc[4 + hq].x += al[4 + hq] * v1.x;  acc[4 + hq].y += al[4 + hq] * v1.y;
            }
        }
    }

    // normalize (fold head-mean), guard deg-0 nodes (reference gives 0 there)
    float2 o0 = make_float2(0.f, 0.f), o1 = make_float2(0.f, 0.f);
#pragma unroll
    for (int hq = 0; hq < 4; hq++) {
        float r0 = (z[hq]     > 0.f) ? 0.25f / z[hq]     : 0.f;
        float r1 = (z[4 + hq] > 0.f) ? 0.25f / z[4 + hq] : 0.f;
        o0.x += acc[hq].x * r0;      o0.y += acc[hq].y * r0;
        o1.x += acc[4 + hq].x * r1;  o1.y += acc[4 + hq].y * r1;
    }

    // epilogue: + mean_h(b_gat) + res, ELU, write x
    int d0 = lane*2;
    float bg0 = 0.25f*(b_gat[d0]   + b_gat[64 + d0]   + b_gat[128 + d0]   + b_gat[192 + d0]);
    float bg1 = 0.25f*(b_gat[d0+1] + b_gat[64 + d0+1] + b_gat[128 + d0+1] + b_gat[192 + d0+1]);

    float2 rv0 = ((const float2*)&g_res[((size_t)(w*2))*HIDD])[lane];
    float2 rv1 = ((const float2*)&g_res[((size_t)(w*2 + 1))*HIDD])[lane];

    float o0x = o0.x + bg0 + rv0.x;
    float o0y = o0.y + bg1 + rv0.y;
    float o1x = o1.x + bg0 + rv1.x;
    float o1y = o1.y + bg1 + rv1.y;
    o0x = o0x > 0.f ? o0x : expm1f(o0x);
    o0y = o0y > 0.f ? o0y : expm1f(o0y);
    o1x = o1x > 0.f ? o1x : expm1f(o1x);
    o1y = o1y > 0.f ? o1y : expm1f(o1y);

    ((float2*)&g_x[((size_t)(w*2))*HIDD])[lane]     = make_float2(o0x, o0y);
    ((float2*)&g_x[((size_t)(w*2 + 1))*HIDD])[lane] = make_float2(o1x, o1y);
}

// ---------------- decoder: out[b,n,:] = x[n,b,:] @ W_dec + b_dec ----------------
__global__ void dec_k(const float* __restrict__ W_dec, const float* __restrict__ b_dec,
                      float* __restrict__ out) {
    int idx = blockIdx.x * blockDim.x + threadIdx.x;
    if (idx >= NB*OUTD) return;
    int o = idx & 7;
    int nb = idx >> 3;
    int n = nb >> 1, b = nb & 1;
    const float* xr = &g_x[(size_t)nb*HIDD];
    float acc = b_dec[o];
#pragma unroll
    for (int k = 0; k < HIDD; k++) acc += xr[k] * W_dec[k*OUTD + o];
    out[((size_t)b*Nn + n)*OUTD + o] = acc;
}

extern "C" void kernel_launch(void* const* d_in, const int* in_sizes, int n_in,
                              void* d_out, int out_size) {
    const float* h     = (const float*)d_in[0];
    const int*   ei    = (const int*)  d_in[1];
    const float* W_enc = (const float*)d_in[2];
    const float* b_enc = (const float*)d_in[3];
    const float* W_gat = (const float*)d_in[4];
    const float* a_l   = (const float*)d_in[5];
    const float* a_r   = (const float*)d_in[6];
    const float* b_gat = (const float*)d_in[7];
    const float* W_res = (const float*)d_in[8];
    const float* b_res = (const float*)d_in[9];
    const float* W_dec = (const float*)d_in[10];
    const float* b_dec = (const float*)d_in[11];
    float* out = (float*)d_out;

    // CSR build (every call; graph-replay safe)
    zero_k<<<(Nn + 255)/256, 256>>>();
    hist_k<<<(Ee + 255)/256, 256>>>(ei);
    scan_k<<<1, 1024>>>();
    fill_k<<<(Ee + 255)/256, 256>>>(ei);

    enc_k<<<(NB*HIDD + 255)/256, 256>>>(h, W_enc, b_enc);

    for (int it = 0; it < 2; ++it) {
        ft_k<<<NB/FTROWS, 256>>>(W_gat, a_l, a_r, W_res, b_res);
        node_agg_k<<<(Nn*32 + 255)/256, 256>>>(b_gat);
    }

    dec_k<<<(NB*OUTD + 255)/256, 256>>>(W_dec, b_dec, out);
}

// round 6
// speedup vs baseline: 1.3586x; 1.2360x over previous
#include <cuda_runtime.h>
#include <cstdint>

// Problem constants
#define Nn 20000
#define Ee 320000
#define Bb 2
#define INF_DIM 32
#define HIDD 64
#define HEADS 4
#define OUTD 8
#define SLOPE 0.2f

#define NB (Nn*Bb)              // 40000
#define FTC (HEADS*HIDD)        // 256

// Scratch (device globals)
__device__ __align__(16) float g_x[NB*HIDD];
__device__ __align__(16) float g_ft[(size_t)NB*FTC];
__device__ __align__(16) float g_res[NB*HIDD];
__device__ float g_el[NB*HEADS];   // [(node*2+b)*4 + h]
__device__ float g_er[NB*HEADS];
__device__ float g_P[HIDD*8];      // [k*8 + q], q<4: Pl, q>=4: Pr
__device__ int g_deg[Nn];
__device__ int g_fill[Nn];
__device__ int g_rowptr[Nn + 1];
__device__ int g_col[Ee];

// ---- packed f32x2 helpers (sm_103a FFMA2) ----
__device__ __forceinline__ uint64_t pk2(float lo, float hi) {
    uint64_t r; asm("mov.b64 %0, {%1,%2};" : "=l"(r) : "f"(lo), "f"(hi)); return r;
}
__device__ __forceinline__ void fma2(uint64_t& acc, uint64_t a, uint64_t b) {
    asm("fma.rn.f32x2 %0, %1, %2, %0;" : "+l"(acc) : "l"(a), "l"(b));
}
__device__ __forceinline__ float2 upk(uint64_t v) {
    float2 r; asm("mov.b64 {%0,%1}, %2;" : "=f"(r.x), "=f"(r.y) : "l"(v)); return r;
}

// ---------------- CSR build ----------------
__global__ void zero_k() {
    int idx = blockIdx.x * blockDim.x + threadIdx.x;
    if (idx < Nn) { g_deg[idx] = 0; g_fill[idx] = 0; }
}

__global__ void hist_k(const int* __restrict__ ei) {
    int idx = blockIdx.x * blockDim.x + threadIdx.x;
    if (idx < Ee) atomicAdd(&g_deg[ei[Ee + idx]], 1);
}

__global__ void scan_k() {
    __shared__ int wsum[32];
    __shared__ int woff[32];
    __shared__ int btot_s;
    int tid = threadIdx.x;
    int lane = tid & 31, wid = tid >> 5;
    int carry = 0;
    for (int base = 0; base < Nn; base += 1024) {
        int i = base + tid;
        int v = (i < Nn) ? g_deg[i] : 0;
        int incl = v;
#pragma unroll
        for (int o = 1; o < 32; o <<= 1) {
            int t = __shfl_up_sync(0xffffffffu, incl, o);
            if (lane >= o) incl += t;
        }
        if (lane == 31) wsum[wid] = incl;
        __syncthreads();
        if (tid < 32) {
            int wv = wsum[tid];
            int wincl = wv;
#pragma unroll
            for (int o = 1; o < 32; o <<= 1) {
                int t = __shfl_up_sync(0xffffffffu, wincl, o);
                if (tid >= o) wincl += t;
            }
            woff[tid] = wincl - wv;
            if (tid == 31) btot_s = wincl;
        }
        __syncthreads();
        if (i < Nn) g_rowptr[i] = carry + woff[wid] + (incl - v);
        int btot = btot_s;
        __syncthreads();
        carry += btot;
    }
    if (tid == 0) g_rowptr[Nn] = carry;
}

__global__ void fill_k(const int* __restrict__ ei) {
    int idx = blockIdx.x * blockDim.x + threadIdx.x;
    if (idx >= Ee) return;
    int d = ei[Ee + idx];
    int pos = g_rowptr[d] + atomicAdd(&g_fill[d], 1);
    g_col[pos] = ei[idx];
}

// ---------------- P = reshape(W_gat)[k, h*64+d] @ a_{l,r}[h, d] ----------------
__global__ void proj_k(const float* __restrict__ W_gat, const float* __restrict__ a_l,
                       const float* __restrict__ a_r) {
    int t = threadIdx.x;          // 512 threads
    int k = t >> 3, q = t & 7;
    int h = q & 3;
    const float* a = (q < 4) ? a_l : a_r;
    float s = 0.f;
#pragma unroll
    for (int d = 0; d < HIDD; d++)
        s += W_gat[k*FTC + h*HIDD + d] * a[h*HIDD + d];
    g_P[k*8 + q] = s;
}

// ---------------- encoder ----------------
__global__ void enc_k(const float* __restrict__ h, const float* __restrict__ W_enc,
                      const float* __restrict__ b_enc) {
    int idx = blockIdx.x * blockDim.x + threadIdx.x;
    if (idx >= NB*HIDD) return;
    int d  = idx & 63;
    int nb = idx >> 6;
    int n = nb >> 1, b = nb & 1;
    const float* hr = &h[((size_t)b*Nn + n)*INF_DIM];
    float acc = b_enc[d];
#pragma unroll
    for (int k = 0; k < INF_DIM; k++) acc += hr[k] * W_enc[k*HIDD + d];
    g_x[idx] = acc;
}

// ---------------- ft = x @ W_gat, res = x @ W_res + b_res, el/er = x @ P ----------------
// 256 threads, 32 rows/block. x stored transposed row-paired: xs2[k][rp] = {x[2rp][k], x[2rp+1][k]}
#define FTROWS 32
#define RP (FTROWS/2)       // 16 row-pairs
#define XPAD 17             // u64 pitch (pad)
__global__ void ft_k(const float* __restrict__ W_gat,
                     const float* __restrict__ W_res, const float* __restrict__ b_res) {
    __shared__ uint64_t xs2[HIDD * XPAD];
    __shared__ float Ps[HIDD * 8];
    int t = threadIdx.x;
    int nb0 = blockIdx.x * FTROWS;

    // load x transposed: float view index k*(2*XPAD) + row
    {
        float* xf = (float*)xs2;
        for (int i = t; i < FTROWS*HIDD; i += 256) {
            int row = i >> 6, k = i & 63;
            xf[k*(2*XPAD) + row] = g_x[(size_t)(nb0 + row)*HIDD + k];
        }
        for (int i = t; i < HIDD*8; i += 256) Ps[i] = g_P[i];
    }
    __syncthreads();

    // main GEMM: thread t owns ft column t, 16 row-pairs via FFMA2
    uint64_t acc[RP];
#pragma unroll
    for (int r = 0; r < RP; r++) acc[r] = 0ull;

    for (int k = 0; k < HIDD; k++) {
        float w = W_gat[k*FTC + t];
        uint64_t w2 = pk2(w, w);
        const uint64_t* xr = &xs2[k*XPAD];
#pragma unroll
        for (int r = 0; r < RP; r++) fma2(acc[r], xr[r], w2);
    }
#pragma unroll
    for (int r = 0; r < RP; r++) {
        float2 v = upk(acc[r]);
        g_ft[((size_t)(nb0 + 2*r))*FTC + t]     = v.x;
        g_ft[((size_t)(nb0 + 2*r + 1))*FTC + t] = v.y;
    }

    // res: thread t -> col c = t&63, row-pairs {q, q+4, q+8, q+12}, q = t>>6
    {
        int c = t & 63, q = t >> 6;
        float bb = b_res[c];
        uint64_t racc[4];
#pragma unroll
        for (int i = 0; i < 4; i++) racc[i] = pk2(bb, bb);
        for (int k = 0; k < HIDD; k++) {
            float w = W_res[k*HIDD + c];
            uint64_t w2 = pk2(w, w);
            const uint64_t* xr = &xs2[k*XPAD];
#pragma unroll
            for (int i = 0; i < 4; i++) fma2(racc[i], xr[q + 4*i], w2);
        }
#pragma unroll
        for (int i = 0; i < 4; i++) {
            float2 v = upk(racc[i]);
            int rp = q + 4*i;
            g_res[(size_t)(nb0 + 2*rp)*HIDD + c]     = v.x;
            g_res[(size_t)(nb0 + 2*rp + 1)*HIDD + c] = v.y;
        }
    }

    // el/er: thread t -> row r = t>>3 (0..31), q = t&7
    {
        int r = t >> 3, q = t & 7;
        const float* xf = (const float*)xs2;
        float s = 0.f;
        for (int k = 0; k < HIDD; k++)
            s += xf[k*(2*XPAD) + r] * Ps[k*8 + q];
        int nb = nb0 + r;
        if (q < 4) g_el[nb*4 + q]       = s;
        else       g_er[nb*4 + (q - 4)] = s;
    }
}

// ---------------- fused node-centric GAT aggregation + update ----------------
// one warp per dst node, both batches. 4 edges' e-values computed in parallel
// (lane = slot*8 + bh). Gather: lane owns b = lane>>4, dims (lane&15)*4..+4, all heads.
__global__ void node_agg_k(const float* __restrict__ b_gat) {
    int w = (blockIdx.x * blockDim.x + threadIdx.x) >> 5;
    int lane = threadIdx.x & 31;
    if (w >= Nn) return;
    int beg = g_rowptr[w], end = g_rowptr[w + 1];

    int bh = lane & 7;                 // for e-computation role
    int b  = lane >> 4;                // for gather role
    int l16 = lane & 15;

    // er[w, bh] -> each lane keeps its own bh value
    float er_v = (lane < 8) ? g_er[w*8 + lane] : 0.f;
    float er_mine = __shfl_sync(0xffffffffu, er_v, bh);

    float zpart = 0.f;
    float4 acc[HEADS];
#pragma unroll
    for (int h = 0; h < HEADS; h++) acc[h] = make_float4(0.f, 0.f, 0.f, 0.f);

    for (int i0 = beg; i0 < end; i0 += 32) {
        int sj = (i0 + lane < end) ? g_col[i0 + lane] : 0;
        int nE = end - i0; if (nE > 32) nE = 32;
        for (int g = 0; g < nE; g += 4) {
            // compute e for 4 edges in parallel across all 32 lanes
            int slot = lane >> 3;
            int s4 = __shfl_sync(0xffffffffu, sj, g + slot);
            bool valid = (g + slot) < nE;
            float e = 0.f;
            if (valid) {
                float v = g_el[s4*8 + bh] + er_mine;
                v = v > 0.f ? v : SLOPE * v;
                e = __expf(v);
            }
            zpart += e;

            int nG = nE - g; if (nG > 4) nG = 4;
#pragma unroll
            for (int gg = 0; gg < 4; gg++) {
                if (gg >= nG) break;
                int s = __shfl_sync(0xffffffffu, sj, g + gg);
                float a0 = __shfl_sync(0xffffffffu, e, gg*8 + b*4 + 0);
                float a1 = __shfl_sync(0xffffffffu, e, gg*8 + b*4 + 1);
                float a2 = __shfl_sync(0xffffffffu, e, gg*8 + b*4 + 2);
                float a3 = __shfl_sync(0xffffffffu, e, gg*8 + b*4 + 3);
                const float4* f = (const float4*)&g_ft[((size_t)(s*2 + b))*FTC];
                float4 v0 = f[l16];
                float4 v1 = f[16 + l16];
                float4 v2 = f[32 + l16];
                float4 v3 = f[48 + l16];
                acc[0].x += a0*v0.x; acc[0].y += a0*v0.y; acc[0].z += a0*v0.z; acc[0].w += a0*v0.w;
                acc[1].x += a1*v1.x; acc[1].y += a1*v1.y; acc[1].z += a1*v1.z; acc[1].w += a1*v1.w;
                acc[2].x += a2*v2.x; acc[2].y += a2*v2.y; acc[2].z += a2*v2.z; acc[2].w += a2*v2.w;
                acc[3].x += a3*v3.x; acc[3].y += a3*v3.y; acc[3].z += a3*v3.z; acc[3].w += a3*v3.w;
            }
        }
    }

    // z reduce: sum over the 4 edge-slots -> lane holds z for its bh
    zpart += __shfl_xor_sync(0xffffffffu, zpart, 8);
    zpart += __shfl_xor_sync(0xffffffffu, zpart, 16);

    // normalize + head-mean: lane needs rz for (b, h=0..3)
    float4 o = make_float4(0.f, 0.f, 0.f, 0.f);
#pragma unroll
    for (int h = 0; h < HEADS; h++) {
        float zh = __shfl_sync(0xffffffffu, zpart, b*4 + h);
        float rz = (zh > 0.f) ? 0.25f / zh : 0.f;
        o.x += acc[h].x * rz; o.y += acc[h].y * rz;
        o.z += acc[h].z * rz; o.w += acc[h].w * rz;
    }

    // epilogue: + mean_h(b_gat) + res, ELU, write x
    int d0 = l16 * 4;
    const float4* bg = (const float4*)b_gat;
    float4 b0 = bg[l16], b1 = bg[16 + l16], b2 = bg[32 + l16], b3 = bg[48 + l16];
    float4 bgm;
    bgm.x = 0.25f*(b0.x + b1.x + b2.x + b3.x);
    bgm.y = 0.25f*(b0.y + b1.y + b2.y + b3.y);
    bgm.z = 0.25f*(b0.z + b1.z + b2.z + b3.z);
    bgm.w = 0.25f*(b0.w + b1.w + b2.w + b3.w);

    float4 rv = *(const float4*)&g_res[((size_t)(w*2 + b))*HIDD + d0];
    float ox = o.x + bgm.x + rv.x;
    float oy = o.y + bgm.y + rv.y;
    float oz = o.z + bgm.z + rv.z;
    float ow = o.w + bgm.w + rv.w;
    ox = ox > 0.f ? ox : expm1f(ox);
    oy = oy > 0.f ? oy : expm1f(oy);
    oz = oz > 0.f ? oz : expm1f(oz);
    ow = ow > 0.f ? ow : expm1f(ow);
    *(float4*)&g_x[((size_t)(w*2 + b))*HIDD + d0] = make_float4(ox, oy, oz, ow);
}

// ---------------- decoder ----------------
__global__ void dec_k(const float* __restrict__ W_dec, const float* __restrict__ b_dec,
                      float* __restrict__ out) {
    int idx = blockIdx.x * blockDim.x + threadIdx.x;
    if (idx >= NB*OUTD) return;
    int o = idx & 7;
    int nb = idx >> 3;
    int n = nb >> 1, b = nb & 1;
    const float* xr = &g_x[(size_t)nb*HIDD];
    float acc = b_dec[o];
#pragma unroll
    for (int k = 0; k < HIDD; k++) acc += xr[k] * W_dec[k*OUTD + o];
    out[((size_t)b*Nn + n)*OUTD + o] = acc;
}

extern "C" void kernel_launch(void* const* d_in, const int* in_sizes, int n_in,
                              void* d_out, int out_size) {
    const float* h     = (const float*)d_in[0];
    const int*   ei    = (const int*)  d_in[1];
    const float* W_enc = (const float*)d_in[2];
    const float* b_enc = (const float*)d_in[3];
    const float* W_gat = (const float*)d_in[4];
    const float* a_l   = (const float*)d_in[5];
    const float* a_r   = (const float*)d_in[6];
    const float* b_gat = (const float*)d_in[7];
    const float* W_res = (const float*)d_in[8];
    const float* b_res = (const float*)d_in[9];
    const float* W_dec = (const float*)d_in[10];
    const float* b_dec = (const float*)d_in[11];
    float* out = (float*)d_out;

    // CSR build (every call; graph-replay safe)
    zero_k<<<(Nn + 255)/256, 256>>>();
    hist_k<<<(Ee + 255)/256, 256>>>(ei);
    scan_k<<<1, 1024>>>();
    fill_k<<<(Ee + 255)/256, 256>>>(ei);

    proj_k<<<1, 512>>>(W_gat, a_l, a_r);
    enc_k<<<(NB*HIDD + 255)/256, 256>>>(h, W_enc, b_enc);

    for (int it = 0; it < 2; ++it) {
        ft_k<<<NB/FTROWS, 256>>>(W_gat, W_res, b_res);
        node_agg_k<<<(Nn*32 + 255)/256, 256>>>(b_gat);
    }

    dec_k<<<(NB*OUTD + 255)/256, 256>>>(W_dec, b_dec, out);
}

// round 7
// speedup vs baseline: 1.3743x; 1.0116x over previous
#include <cuda_runtime.h>
#include <cuda_fp16.h>
#include <cstdint>

// Problem constants
#define Nn 20000
#define Ee 320000
#define Bb 2
#define INF_DIM 32
#define HIDD 64
#define HEADS 4
#define OUTD 8
#define SLOPE 0.2f

#define NB (Nn*Bb)              // 40000
#define FTC (HEADS*HIDD)        // 256

// Scratch (device globals)
__device__ __align__(16) float g_x[NB*HIDD];
__device__ __align__(16) __half g_fth[(size_t)NB*FTC];   // ft in fp16
__device__ __align__(16) float g_res[NB*HIDD];
__device__ float g_el[NB*HEADS];   // [(node*2+b)*4 + h]
__device__ float g_er[NB*HEADS];
__device__ float g_P[HIDD*8];      // [k*8 + q], q<4: Pl, q>=4: Pr
__device__ int g_deg[Nn];
__device__ int g_fill[Nn];
__device__ int g_rowptr[Nn + 1];
__device__ int g_col[Ee];

// ---- packed f32x2 helpers (sm_103a FFMA2) ----
__device__ __forceinline__ uint64_t pk2(float lo, float hi) {
    uint64_t r; asm("mov.b64 %0, {%1,%2};" : "=l"(r) : "f"(lo), "f"(hi)); return r;
}
__device__ __forceinline__ void fma2(uint64_t& acc, uint64_t a, uint64_t b) {
    asm("fma.rn.f32x2 %0, %1, %2, %0;" : "+l"(acc) : "l"(a), "l"(b));
}
__device__ __forceinline__ float2 upk(uint64_t v) {
    float2 r; asm("mov.b64 {%0,%1}, %2;" : "=f"(r.x), "=f"(r.y) : "l"(v)); return r;
}

// ---------------- CSR build ----------------
__global__ void zero_k() {
    int idx = blockIdx.x * blockDim.x + threadIdx.x;
    if (idx < Nn) { g_deg[idx] = 0; g_fill[idx] = 0; }
}

__global__ void hist_k(const int* __restrict__ ei) {
    int idx = blockIdx.x * blockDim.x + threadIdx.x;
    if (idx < Ee) atomicAdd(&g_deg[ei[Ee + idx]], 1);
}

__global__ void scan_k() {
    __shared__ int wsum[32];
    __shared__ int woff[32];
    __shared__ int btot_s;
    int tid = threadIdx.x;
    int lane = tid & 31, wid = tid >> 5;
    int carry = 0;
    for (int base = 0; base < Nn; base += 1024) {
        int i = base + tid;
        int v = (i < Nn) ? g_deg[i] : 0;
        int incl = v;
#pragma unroll
        for (int o = 1; o < 32; o <<= 1) {
            int t = __shfl_up_sync(0xffffffffu, incl, o);
            if (lane >= o) incl += t;
        }
        if (lane == 31) wsum[wid] = incl;
        __syncthreads();
        if (tid < 32) {
            int wv = wsum[tid];
            int wincl = wv;
#pragma unroll
            for (int o = 1; o < 32; o <<= 1) {
                int t = __shfl_up_sync(0xffffffffu, wincl, o);
                if (tid >= o) wincl += t;
            }
            woff[tid] = wincl - wv;
            if (tid == 31) btot_s = wincl;
        }
        __syncthreads();
        if (i < Nn) g_rowptr[i] = carry + woff[wid] + (incl - v);
        int btot = btot_s;
        __syncthreads();
        carry += btot;
    }
    if (tid == 0) g_rowptr[Nn] = carry;
}

__global__ void fill_k(const int* __restrict__ ei) {
    int idx = blockIdx.x * blockDim.x + threadIdx.x;
    if (idx >= Ee) return;
    int d = ei[Ee + idx];
    int pos = g_rowptr[d] + atomicAdd(&g_fill[d], 1);
    g_col[pos] = ei[idx];
}

// ---------------- P = reshape(W_gat)[k, h*64+d] @ a_{l,r}[h, d] ----------------
__global__ void proj_k(const float* __restrict__ W_gat, const float* __restrict__ a_l,
                       const float* __restrict__ a_r) {
    int t = threadIdx.x;          // 512 threads
    int k = t >> 3, q = t & 7;
    int h = q & 3;
    const float* a = (q < 4) ? a_l : a_r;
    float s = 0.f;
#pragma unroll
    for (int d = 0; d < HIDD; d++)
        s += W_gat[k*FTC + h*HIDD + d] * a[h*HIDD + d];
    g_P[k*8 + q] = s;
}

// ---------------- encoder ----------------
__global__ void enc_k(const float* __restrict__ h, const float* __restrict__ W_enc,
                      const float* __restrict__ b_enc) {
    int idx = blockIdx.x * blockDim.x + threadIdx.x;
    if (idx >= NB*HIDD) return;
    int d  = idx & 63;
    int nb = idx >> 6;
    int n = nb >> 1, b = nb & 1;
    const float* hr = &h[((size_t)b*Nn + n)*INF_DIM];
    float acc = b_enc[d];
#pragma unroll
    for (int k = 0; k < INF_DIM; k++) acc += hr[k] * W_enc[k*HIDD + d];
    g_x[idx] = acc;
}

// ---------------- ft = x @ W_gat (fp16 out), res = x @ W_res + b_res, el/er = x @ P ----------------
// 256 threads, 32 rows/block. x stored transposed row-paired: xs2[k][rp] = {x[2rp][k], x[2rp+1][k]}
#define FTROWS 32
#define RP (FTROWS/2)       // 16 row-pairs
#define XPAD 17             // u64 pitch (pad)
__global__ void ft_k(const float* __restrict__ W_gat,
                     const float* __restrict__ W_res, const float* __restrict__ b_res) {
    __shared__ uint64_t xs2[HIDD * XPAD];
    __shared__ float Ps[HIDD * 8];
    int t = threadIdx.x;
    int nb0 = blockIdx.x * FTROWS;

    {
        float* xf = (float*)xs2;
        for (int i = t; i < FTROWS*HIDD; i += 256) {
            int row = i >> 6, k = i & 63;
            xf[k*(2*XPAD) + row] = g_x[(size_t)(nb0 + row)*HIDD + k];
        }
        for (int i = t; i < HIDD*8; i += 256) Ps[i] = g_P[i];
    }
    __syncthreads();

    // main GEMM: thread t owns ft column t, 16 row-pairs via FFMA2
    uint64_t acc[RP];
#pragma unroll
    for (int r = 0; r < RP; r++) acc[r] = 0ull;

    for (int k = 0; k < HIDD; k++) {
        float w = W_gat[k*FTC + t];
        uint64_t w2 = pk2(w, w);
        const uint64_t* xr = &xs2[k*XPAD];
#pragma unroll
        for (int r = 0; r < RP; r++) fma2(acc[r], xr[r], w2);
    }
#pragma unroll
    for (int r = 0; r < RP; r++) {
        float2 v = upk(acc[r]);
        g_fth[((size_t)(nb0 + 2*r))*FTC + t]     = __float2half_rn(v.x);
        g_fth[((size_t)(nb0 + 2*r + 1))*FTC + t] = __float2half_rn(v.y);
    }

    // res: thread t -> col c = t&63, row-pairs {q, q+4, q+8, q+12}, q = t>>6
    {
        int c = t & 63, q = t >> 6;
        float bb = b_res[c];
        uint64_t racc[4];
#pragma unroll
        for (int i = 0; i < 4; i++) racc[i] = pk2(bb, bb);
        for (int k = 0; k < HIDD; k++) {
            float w = W_res[k*HIDD + c];
            uint64_t w2 = pk2(w, w);
            const uint64_t* xr = &xs2[k*XPAD];
#pragma unroll
            for (int i = 0; i < 4; i++) fma2(racc[i], xr[q + 4*i], w2);
        }
#pragma unroll
        for (int i = 0; i < 4; i++) {
            float2 v = upk(racc[i]);
            int rp = q + 4*i;
            g_res[(size_t)(nb0 + 2*rp)*HIDD + c]     = v.x;
            g_res[(size_t)(nb0 + 2*rp + 1)*HIDD + c] = v.y;
        }
    }

    // el/er: thread t -> row r = t>>3 (0..31), q = t&7
    {
        int r = t >> 3, q = t & 7;
        const float* xf = (const float*)xs2;
        float s = 0.f;
        for (int k = 0; k < HIDD; k++)
            s += xf[k*(2*XPAD) + r] * Ps[k*8 + q];
        int nb = nb0 + r;
        if (q < 4) g_el[nb*4 + q]       = s;
        else       g_er[nb*4 + (q - 4)] = s;
    }
}

// ---------------- fused node-centric GAT aggregation + update (+ optional decoder) ----------------
// one warp per dst node, both batches. 4 edges' e-values computed in parallel.
// Gather in fp16 (uint2 = 4 dims per head), accumulate fp32.
__global__ void node_agg_k(const float* __restrict__ b_gat,
                           const float* __restrict__ W_dec, const float* __restrict__ b_dec,
                           float* __restrict__ out, int last) {
    int w = (blockIdx.x * blockDim.x + threadIdx.x) >> 5;
    int lane = threadIdx.x & 31;
    if (w >= Nn) return;
    int beg = g_rowptr[w], end = g_rowptr[w + 1];

    int bh = lane & 7;                 // e-computation role
    int b  = lane >> 4;                // gather role: batch
    int l16 = lane & 15;               // gather role: dim-quad

    float er_v = (lane < 8) ? g_er[w*8 + lane] : 0.f;
    float er_mine = __shfl_sync(0xffffffffu, er_v, bh);

    float zpart = 0.f;
    float4 acc[HEADS];
#pragma unroll
    for (int h = 0; h < HEADS; h++) acc[h] = make_float4(0.f, 0.f, 0.f, 0.f);

    for (int i0 = beg; i0 < end; i0 += 32) {
        int sj = (i0 + lane < end) ? g_col[i0 + lane] : 0;
        int nE = end - i0; if (nE > 32) nE = 32;
        for (int g = 0; g < nE; g += 4) {
            int slot = lane >> 3;
            int s4 = __shfl_sync(0xffffffffu, sj, g + slot);
            bool valid = (g + slot) < nE;
            float e = 0.f;
            if (valid) {
                float v = g_el[s4*8 + bh] + er_mine;
                v = v > 0.f ? v : SLOPE * v;
                e = __expf(v);
            }
            zpart += e;

            int nG = nE - g; if (nG > 4) nG = 4;
#pragma unroll
            for (int gg = 0; gg < 4; gg++) {
                if (gg >= nG) break;
                int s = __shfl_sync(0xffffffffu, sj, g + gg);
                float a0 = __shfl_sync(0xffffffffu, e, gg*8 + b*4 + 0);
                float a1 = __shfl_sync(0xffffffffu, e, gg*8 + b*4 + 1);
                float a2 = __shfl_sync(0xffffffffu, e, gg*8 + b*4 + 2);
                float a3 = __shfl_sync(0xffffffffu, e, gg*8 + b*4 + 3);
                const uint2* f = (const uint2*)&g_fth[((size_t)(s*2 + b))*FTC];
                uint2 u0 = f[l16];
                uint2 u1 = f[16 + l16];
                uint2 u2 = f[32 + l16];
                uint2 u3 = f[48 + l16];
                float2 p, q;
                p = __half22float2(*(__half2*)&u0.x); q = __half22float2(*(__half2*)&u0.y);
                acc[0].x += a0*p.x; acc[0].y += a0*p.y; acc[0].z += a0*q.x; acc[0].w += a0*q.y;
                p = __half22float2(*(__half2*)&u1.x); q = __half22float2(*(__half2*)&u1.y);
                acc[1].x += a1*p.x; acc[1].y += a1*p.y; acc[1].z += a1*q.x; acc[1].w += a1*q.y;
                p = __half22float2(*(__half2*)&u2.x); q = __half22float2(*(__half2*)&u2.y);
                acc[2].x += a2*p.x; acc[2].y += a2*p.y; acc[2].z += a2*q.x; acc[2].w += a2*q.y;
                p = __half22float2(*(__half2*)&u3.x); q = __half22float2(*(__half2*)&u3.y);
                acc[3].x += a3*p.x; acc[3].y += a3*p.y; acc[3].z += a3*q.x; acc[3].w += a3*q.y;
            }
        }
    }

    // z reduce: sum over the 4 edge-slots -> lane holds z for its bh
    zpart += __shfl_xor_sync(0xffffffffu, zpart, 8);
    zpart += __shfl_xor_sync(0xffffffffu, zpart, 16);

    // normalize + head-mean
    float4 o = make_float4(0.f, 0.f, 0.f, 0.f);
#pragma unroll
    for (int h = 0; h < HEADS; h++) {
        float zh = __shfl_sync(0xffffffffu, zpart, b*4 + h);
        float rz = (zh > 0.f) ? 0.25f / zh : 0.f;
        o.x += acc[h].x * rz; o.y += acc[h].y * rz;
        o.z += acc[h].z * rz; o.w += acc[h].w * rz;
    }

    // epilogue: + mean_h(b_gat) + res, ELU
    int d0 = l16 * 4;
    const float4* bg = (const float4*)b_gat;
    float4 b0 = bg[l16], b1 = bg[16 + l16], b2 = bg[32 + l16], b3 = bg[48 + l16];
    float4 bgm;
    bgm.x = 0.25f*(b0.x + b1.x + b2.x + b3.x);
    bgm.y = 0.25f*(b0.y + b1.y + b2.y + b3.y);
    bgm.z = 0.25f*(b0.z + b1.z + b2.z + b3.z);
    bgm.w = 0.25f*(b0.w + b1.w + b2.w + b3.w);

    float4 rv = *(const float4*)&g_res[((size_t)(w*2 + b))*HIDD + d0];
    float ox = o.x + bgm.x + rv.x;
    float oy = o.y + bgm.y + rv.y;
    float oz = o.z + bgm.z + rv.z;
    float ow = o.w + bgm.w + rv.w;
    ox = ox > 0.f ? ox : expm1f(ox);
    oy = oy > 0.f ? oy : expm1f(oy);
    oz = oz > 0.f ? oz : expm1f(oz);
    ow = ow > 0.f ? ow : expm1f(ow);

    if (!last) {
        *(float4*)&g_x[((size_t)(w*2 + b))*HIDD + d0] = make_float4(ox, oy, oz, ow);
    } else {
        // fused decoder: out[b, w, :] = x[w, b, :] @ W_dec + b_dec
        float po[OUTD];
        const float4* W0 = (const float4*)&W_dec[(d0 + 0)*OUTD];
        const float4* W1 = (const float4*)&W_dec[(d0 + 1)*OUTD];
        const float4* W2 = (const float4*)&W_dec[(d0 + 2)*OUTD];
        const float4* W3 = (const float4*)&W_dec[(d0 + 3)*OUTD];
        float4 wa, wb;
        wa = W0[0]; wb = W0[1];
        po[0] = ox*wa.x; po[1] = ox*wa.y; po[2] = ox*wa.z; po[3] = ox*wa.w;
        po[4] = ox*wb.x; po[5] = ox*wb.y; po[6] = ox*wb.z; po[7] = ox*wb.w;
        wa = W1[0]; wb = W1[1];
        po[0] += oy*wa.x; po[1] += oy*wa.y; po[2] += oy*wa.z; po[3] += oy*wa.w;
        po[4] += oy*wb.x; po[5] += oy*wb.y; po[6] += oy*wb.z; po[7] += oy*wb.w;
        wa = W2[0]; wb = W2[1];
        po[0] += oz*wa.x; po[1] += oz*wa.y; po[2] += oz*wa.z; po[3] += oz*wa.w;
        po[4] += oz*wb.x; po[5] += oz*wb.y; po[6] += oz*wb.z; po[7] += oz*wb.w;
        wa = W3[0]; wb = W3[1];
        po[0] += ow*wa.x; po[1] += ow*wa.y; po[2] += ow*wa.z; po[3] += ow*wa.w;
        po[4] += ow*wb.x; po[5] += ow*wb.y; po[6] += ow*wb.z; po[7] += ow*wb.w;
#pragma unroll
        for (int off = 1; off < 16; off <<= 1)
#pragma unroll
            for (int oo = 0; oo < OUTD; oo++)
                po[oo] += __shfl_xor_sync(0xffffffffu, po[oo], off);
        if (l16 == 0) {
            float* op = &out[((size_t)b*Nn + w)*OUTD];
            float4 v0 = make_float4(po[0] + b_dec[0], po[1] + b_dec[1],
                                    po[2] + b_dec[2], po[3] + b_dec[3]);
            float4 v1 = make_float4(po[4] + b_dec[4], po[5] + b_dec[5],
                                    po[6] + b_dec[6], po[7] + b_dec[7]);
            *(float4*)&op[0] = v0;
            *(float4*)&op[4] = v1;
        }
    }
}

extern "C" void kernel_launch(void* const* d_in, const int* in_sizes, int n_in,
                              void* d_out, int out_size) {
    const float* h     = (const float*)d_in[0];
    const int*   ei    = (const int*)  d_in[1];
    const float* W_enc = (const float*)d_in[2];
    const float* b_enc = (const float*)d_in[3];
    const float* W_gat = (const float*)d_in[4];
    const float* a_l   = (const float*)d_in[5];
    const float* a_r   = (const float*)d_in[6];
    const float* b_gat = (const float*)d_in[7];
    const float* W_res = (const float*)d_in[8];
    const float* b_res = (const float*)d_in[9];
    const float* W_dec = (const float*)d_in[10];
    const float* b_dec = (const float*)d_in[11];
    float* out = (float*)d_out;

    // CSR build (every call; graph-replay safe)
    zero_k<<<(Nn + 255)/256, 256>>>();
    hist_k<<<(Ee + 255)/256, 256>>>(ei);
    scan_k<<<1, 1024>>>();
    fill_k<<<(Ee + 255)/256, 256>>>(ei);

    proj_k<<<1, 512>>>(W_gat, a_l, a_r);
    enc_k<<<(NB*HIDD + 255)/256, 256>>>(h, W_enc, b_enc);

    for (int it = 0; it < 2; ++it) {
        ft_k<<<NB/FTROWS, 256>>>(W_gat, W_res, b_res);
        node_agg_k<<<(Nn*32 + 255)/256, 256>>>(b_gat, W_dec, b_dec, out, it == 1);
    }
}